// round 12
// baseline (speedup 1.0000x reference)
#include <cuda_runtime.h>
#include <cuda_fp16.h>
#include <cstdint>
#include <cstring>

// Problem constants
#define T_PADDED 65656
#define T_OUT    65536
#define NROWS    768
#define CCH      384
#define NB       168
#define HOP      392
#define OVL      120
#define NCOLS    (NROWS * NB)   // 129024

#define SWZ(x) ((x) ^ (((x) >> 3) & 0x70))

// ---------------- device globals (allocation-free rule) ----------------
__device__ float  g_h[512];
__device__ uint4  g_Bc[4 * 7 * 1024];              // circulant fp16 tiles [jt][kc], 16KB, SW128
__device__ uint4  g_Bw[3 * 6 * 1024];              // W fp16 tiles [dt][kc]
__device__ __half g_C[(size_t)NB * 512 * NROWS];   // fp16 [b][j][r]

// ---------------- helpers ----------------
__device__ __forceinline__ uint32_t smem_u32(const void* p) {
    uint32_t a;
    asm("{ .reg .u64 t; cvta.to.shared.u64 t, %1; cvt.u32.u64 %0, t; }" : "=r"(a) : "l"(p));
    return a;
}
__device__ __forceinline__ void ldm4(uint32_t addr, uint32_t* r) {
    asm volatile("ldmatrix.sync.aligned.m8n8.x4.shared.b16 {%0,%1,%2,%3}, [%4];"
                 : "=r"(r[0]), "=r"(r[1]), "=r"(r[2]), "=r"(r[3]) : "r"(addr));
}
__device__ __forceinline__ void mma16816(float* c, const uint32_t* a, const uint32_t* b) {
    asm volatile("mma.sync.aligned.m16n8k16.row.col.f32.f16.f16.f32 "
                 "{%0,%1,%2,%3},{%4,%5,%6,%7},{%8,%9},{%0,%1,%2,%3};"
                 : "+f"(c[0]), "+f"(c[1]), "+f"(c[2]), "+f"(c[3])
                 : "r"(a[0]), "r"(a[1]), "r"(a[2]), "r"(a[3]), "r"(b[0]), "r"(b[1]));
}
__device__ __forceinline__ unsigned hadd2u(unsigned a, unsigned b) {
    __half2 x, y; memcpy(&x, &a, 4); memcpy(&y, &b, 4);
    __half2 z = __hadd2(x, y);
    unsigned u; memcpy(&u, &z, 4); return u;
}
__device__ __forceinline__ unsigned f22u(float a, float b) {
    __half2 h = __floats2half2_rn(a, b);
    unsigned u; memcpy(&u, &h, 4); return u;
}
#define CP16(s, g)     asm volatile("cp.async.cg.shared.global [%0], [%1], 16;" :: "r"(s), "l"(g))
#define CP_COMMIT()    asm volatile("cp.async.commit_group;" ::: "memory")
#define CP_WAIT1()     asm volatile("cp.async.wait_group 1;" ::: "memory")

// ---------------- kernel 1: h = irfft(H, 512) ----------------
__global__ void k_irfft(const float* __restrict__ H) {
    int j = threadIdx.x;
    float acc = H[0] + ((j & 1) ? -H[256] : H[256]);
    const float w = 6.283185307179586476f / 512.0f;
    for (int m = 1; m < 256; m++) {
        int ph = (m * j) & 511;
        acc += 2.0f * H[m] * cosf(w * (float)ph);
    }
    g_h[j] = acc * (1.0f / 512.0f);
}

// ---------------- kernel 1b: build circulant + W tiles (merged) ----------------
// blocks 0..27: circulant tiles [jt][kc] (jt = blk/7, kc = blk%7)
// blocks 28..45: W tiles [dt][kc]       (dt = w/6,  kc = w%6)
__global__ void k_build(const float* __restrict__ vt, const float* __restrict__ sstd) {
    const int tid = threadIdx.x;
    if (blockIdx.x < 28) {
        __shared__ float sh[512];
        int jt = blockIdx.x / 7, kc = blockIdx.x % 7;
        sh[tid] = g_h[tid]; sh[tid + 256] = g_h[tid + 256];
        __syncthreads();
        char* dst = (char*)g_Bc + (size_t)(jt * 7 + kc) * 16384;
        for (int e = tid; e < 8192; e += 256) {
            int jl = e >> 6, kl = e & 63;
            int k = kc * 64 + kl;
            float v = (k < HOP) ? sh[(jt * 128 + jl - k) & 511] : 0.0f;
            *(__half*)(dst + SWZ(jl * 128 + kl * 2)) = __float2half_rn(v);
        }
    } else {
        int w = blockIdx.x - 28;
        int dt = w / 6, kc = w % 6;
        char* dst = (char*)g_Bw + (size_t)(dt * 6 + kc) * 16384;
        for (int e = tid; e < 8192; e += 256) {
            int kl = e >> 7, dl = e & 127;
            int c = kc * 64 + kl, d = dt * 128 + dl;
            float v = sstd[c] * vt[c * CCH + d];
            *(__half*)(dst + SWZ(dl * 128 + kl * 2)) = __float2half_rn(v);
        }
    }
}

// ============================================================================
// fp16 warp-MMA engine. Stage s at s*32768: A @+0 (128x128B, SW128), B @+16384.
// 8 warps: wm = wid>>2 (2) x wn = wid&3 (4); warp tile 64m x 32n.
// Templated kstep range so copy-issue can be interleaved between halves.
// ============================================================================
template <int KS0, int KS1>
__device__ __forceinline__ void gemm16(uint32_t sb, int s, int wm, int wn,
                                       int lane, float acc[4][4][4]) {
    const uint32_t sx = (lane & 7) << 4;
    const int kA_l = (lane & 16) >> 1;
    const int kB_l = lane & 8;
    const int mrow = lane & 15;
    const int nrow = (lane & 7) + ((lane & 16) >> 1);
    const uint32_t aBase = sb + s * 32768 + (wm * 64 + mrow) * 128;
    const uint32_t bBase = sb + s * 32768 + 16384 + (wn * 32 + nrow) * 128;

#pragma unroll
    for (int ks = KS0; ks < KS1; ks++) {
        const uint32_t ka = ((uint32_t)(ks * 16 + kA_l) * 2) ^ sx;
        const uint32_t kb = ((uint32_t)(ks * 16 + kB_l) * 2) ^ sx;
        uint32_t bh[4][2];
#pragma unroll
        for (int p = 0; p < 2; p++) {
            uint32_t r[4];
            ldm4(bBase + p * 2048 + kb, r);
            bh[2 * p][0] = r[0]; bh[2 * p][1] = r[1];
            bh[2 * p + 1][0] = r[2]; bh[2 * p + 1][1] = r[3];
        }
#pragma unroll
        for (int mf = 0; mf < 4; mf++) {
            uint32_t ah[4];
            ldm4(aBase + mf * 2048 + ka, ah);
#pragma unroll
            for (int nf = 0; nf < 4; nf++)
                mma16816(acc[mf][nf], ah, bh[nf]);
        }
    }
}

// ---------------- kernel 2: conv GEMM (truncation fused) ----------------
// D[r][j] for block b: m = r (A = fp32 noise, LDG+cvt+STS), n = j (B = circ tiles).
// Grid (jt, b*6+rt): jt fastest so co-resident CTAs share fp32 noise in L2.
// 3-stage pipeline, single sync per chunk, copy-issue interleaved.
// Epilogue transposes through smem -> g_C[b][j][r] (r contiguous).
__global__ __launch_bounds__(256, 2) void k_conv_mma(const float* __restrict__ noise) {
    extern __shared__ char smem[];
    const uint32_t sb = smem_u32(smem);
    const int tid = threadIdx.x, lane = tid & 31, wid = tid >> 5;
    const int wm = wid >> 2, wn = wid & 3;
    const int jt = blockIdx.x;
    const int b  = blockIdx.y / 6;
    const int rt = blockIdx.y % 6;

    const int row = tid >> 1;
    const int segf = (tid & 1) * 32;      // float offset within chunk
    const int segB = (tid & 1) * 64;      // byte offset in smem row
    const uint32_t rowbase = row * 128;
    const uint32_t rxor = (row & 7) << 4;
    const float* nrow32 = noise + (size_t)(rt * 128 + row) * T_PADDED + b * HOP;
    const int krel = T_PADDED - b * HOP;  // valid floats from chunk origin

    float acc[4][4][4];
#pragma unroll
    for (int i = 0; i < 4; i++)
#pragma unroll
        for (int j = 0; j < 4; j++)
#pragma unroll
            for (int q = 0; q < 4; q++) acc[i][j][q] = 0.0f;

    uint4 pf[4];

#define CONV_LDG(cc) do { \
    const int kk = (cc) * 64 + segf; \
    _Pragma("unroll") \
    for (int i = 0; i < 4; i++) { \
        float4 lo = (kk + i * 8 < krel)     ? *(const float4*)(nrow32 + kk + i * 8) \
                                            : make_float4(0.f, 0.f, 0.f, 0.f); \
        float4 hi = (kk + i * 8 + 4 < krel) ? *(const float4*)(nrow32 + kk + i * 8 + 4) \
                                            : make_float4(0.f, 0.f, 0.f, 0.f); \
        pf[i].x = f22u(lo.x, lo.y); pf[i].y = f22u(lo.z, lo.w); \
        pf[i].z = f22u(hi.x, hi.y); pf[i].w = f22u(hi.z, hi.w); \
    } \
} while (0)
#define CONV_STS(s) do { \
    _Pragma("unroll") \
    for (int i = 0; i < 4; i++) \
        *(uint4*)(smem + (s) * 32768 + rowbase + ((segB + i * 16) ^ rxor)) = pf[i]; \
} while (0)
#define CONV_CPB(cc, s) do { \
    const char* srcB = (const char*)(g_Bc + (size_t)(jt * 7 + (cc)) * 1024) + tid * 16; \
    uint32_t dB = sb + (s) * 32768 + 16384 + tid * 16; \
    _Pragma("unroll") \
    for (int i = 0; i < 4; i++) CP16(dB + i * 4096, srcB + i * 4096); \
} while (0)

    // prologue: stages 0,1 filled; pf = chunk 2
    CONV_LDG(0); CONV_STS(0);
    CONV_LDG(1); CONV_STS(1);
    CONV_CPB(0, 0); CP_COMMIT();
    CONV_CPB(1, 1); CP_COMMIT();
    CONV_LDG(2);

#pragma unroll 1
    for (int c = 0; c < 6; c++) {
        CP_WAIT1();                        // B(c) landed (this thread)
        __syncthreads();                   // copies + STS visible; stage (c+2)%3 free
        gemm16<0, 2>(sb, c % 3, wm, wn, lane, acc);
        if (c + 2 < 7) {
            CONV_CPB(c + 2, (c + 2) % 3);
            CONV_STS((c + 2) % 3);         // pf holds chunk c+2
        }
        CP_COMMIT();                       // unconditional: 1 group / iteration
        if (c + 3 < 7) CONV_LDG(c + 3);    // refill pf
        gemm16<2, 4>(sb, c % 3, wm, wn, lane, acc);
    }
    // tail chunk c = 6 (1 kstep; K=392 ends inside kstep 0 of chunk 6)
    CP_WAIT1();
    __syncthreads();
    gemm16<0, 1>(sb, 0 /* 6%3 */, wm, wn, lane, acc);

    // epilogue: transpose through smem, write g_C[b][j][r] (r contiguous)
    __syncthreads();
    {
        __half* st = (__half*)smem;       // [j][136] halves, 34816 B
#pragma unroll
        for (int mf = 0; mf < 4; mf++) {
            int m = wm * 64 + mf * 16 + (lane >> 2);
#pragma unroll
            for (int nf = 0; nf < 4; nf++) {
                int j = wn * 32 + nf * 8 + (lane & 3) * 2;
                st[j * 136 + m]           = __float2half_rn(acc[mf][nf][0]);
                st[(j + 1) * 136 + m]     = __float2half_rn(acc[mf][nf][1]);
                st[j * 136 + m + 8]       = __float2half_rn(acc[mf][nf][2]);
                st[(j + 1) * 136 + m + 8] = __float2half_rn(acc[mf][nf][3]);
            }
        }
        __syncthreads();
        const int jl = tid >> 1;
        const int sg = (tid & 1) * 64;    // halves
        const uint4* src = (const uint4*)(st + jl * 136 + sg);
        uint4* dst = (uint4*)(g_C + (size_t)(b * 512 + jt * 128 + jl) * 768 + rt * 128 + sg);
#pragma unroll
        for (int i = 0; i < 8; i++) dst[i] = src[i];
    }
#undef CONV_LDG
#undef CONV_STS
#undef CONV_CPB
}

// ---------------- kernel 3: fused overlap-add + dewhiten GEMM ----------------
// out[nz][t][d] = sum_c y[t][c] * W[d][c],
//   y[t][c] = C[b2][j2][nz*384+c] (+ C[b2-1][j2+392][nz*384+c] if j2<120)
// m = t (A via LDG + hadd2 + STS), n = d (B = W tiles via cp.async).
// 3-stage, single sync per chunk, copy-issue interleaved between gemm halves.
__global__ __launch_bounds__(256, 2) void k_out_mma(float* __restrict__ out) {
    extern __shared__ char smem[];
    const uint32_t sb = smem_u32(smem);
    const int tid = threadIdx.x, lane = tid & 31, wid = tid >> 5;
    const int wm = wid >> 2, wn = wid & 3;
    const int dt = blockIdx.x;
    const int t0 = blockIdx.y * 128;
    const int nz = blockIdx.z;

    const int row = tid >> 1;
    const int segh = (tid & 1) * 32;      // half offset within chunk
    const int segB = (tid & 1) * 64;      // byte offset
    const uint32_t rowbase = row * 128;
    const uint32_t rxor = (row & 7) << 4;

    const int t = t0 + row;
    const int p = t + OVL;
    const int b2 = p / HOP;
    const int j2 = p - b2 * HOP;
    const __half* ybase = g_C + (size_t)(b2 * 512 + j2) * 768 + nz * CCH;
    const bool ov = (j2 < OVL);

    float acc[4][4][4];
#pragma unroll
    for (int i = 0; i < 4; i++)
#pragma unroll
        for (int j = 0; j < 4; j++)
#pragma unroll
            for (int q = 0; q < 4; q++) acc[i][j][q] = 0.0f;

    uint4 pf[4];

#define OUT_LDG(cc) do { \
    const int kk = (cc) * 64 + segh; \
    _Pragma("unroll") \
    for (int i = 0; i < 4; i++) { \
        uint4 v = *(const uint4*)(ybase + kk + i * 8); \
        if (ov) { \
            uint4 w = *(const uint4*)(ybase + kk + i * 8 - 92160); \
            v.x = hadd2u(v.x, w.x); v.y = hadd2u(v.y, w.y); \
            v.z = hadd2u(v.z, w.z); v.w = hadd2u(v.w, w.w); \
        } \
        pf[i] = v; \
    } \
} while (0)
#define OUT_STS(s) do { \
    _Pragma("unroll") \
    for (int i = 0; i < 4; i++) \
        *(uint4*)(smem + (s) * 32768 + rowbase + ((segB + i * 16) ^ rxor)) = pf[i]; \
} while (0)
#define OUT_CPB(cc, s) do { \
    const char* srcB = (const char*)(g_Bw + (size_t)(dt * 6 + (cc)) * 1024) + tid * 16; \
    uint32_t dB = sb + (s) * 32768 + 16384 + tid * 16; \
    _Pragma("unroll") \
    for (int i = 0; i < 4; i++) CP16(dB + i * 4096, srcB + i * 4096); \
} while (0)

    // prologue: stages 0,1 filled; pf = chunk 2
    OUT_LDG(0); OUT_STS(0);
    OUT_LDG(1); OUT_STS(1);
    OUT_CPB(0, 0); CP_COMMIT();
    OUT_CPB(1, 1); CP_COMMIT();
    OUT_LDG(2);

#pragma unroll 1
    for (int c = 0; c < 6; c++) {
        CP_WAIT1();                        // B(c) landed (this thread)
        __syncthreads();                   // copies + STS(c) visible; stage (c+2)%3 free
        gemm16<0, 2>(sb, c % 3, wm, wn, lane, acc);
        if (c + 2 < 6) {
            OUT_CPB(c + 2, (c + 2) % 3);
            OUT_STS((c + 2) % 3);          // pf holds chunk c+2
        }
        CP_COMMIT();                       // unconditional: 1 group / iteration
        if (c + 3 < 6) OUT_LDG(c + 3);     // refill pf
        gemm16<2, 4>(sb, c % 3, wm, wn, lane, acc);
    }

    // epilogue: out[(nz*T + t)*384 + d]
    const int tb = t0 + wm * 64;
    const int db = dt * 128 + wn * 32;
#pragma unroll
    for (int mf = 0; mf < 4; mf++) {
        int tt = tb + mf * 16 + (lane >> 2);
        float* ob0 = out + ((size_t)nz * T_OUT + tt) * CCH;
        float* ob1 = out + ((size_t)nz * T_OUT + tt + 8) * CCH;
#pragma unroll
        for (int nf = 0; nf < 4; nf++) {
            int d = db + nf * 8 + (lane & 3) * 2;
            *(float2*)(ob0 + d) = make_float2(acc[mf][nf][0], acc[mf][nf][1]);
            *(float2*)(ob1 + d) = make_float2(acc[mf][nf][2], acc[mf][nf][3]);
        }
    }
#undef OUT_LDG
#undef OUT_STS
#undef OUT_CPB
}

// ---------------------------------------------------------------------------
extern "C" void kernel_launch(void* const* d_in, const int* in_sizes, int n_in,
                              void* d_out, int out_size) {
    const float* noise = (const float*)d_in[0];   // [768, 65656]
    const float* sstd  = (const float*)d_in[1];   // [384]
    const float* vt    = (const float*)d_in[2];   // [384, 384]
    const float* H     = (const float*)d_in[3];   // [257]
    float* out = (float*)d_out;                   // [2, 65536, 384]

    cudaFuncSetAttribute(k_conv_mma, cudaFuncAttributeMaxDynamicSharedMemorySize, 98304);
    cudaFuncSetAttribute(k_out_mma,  cudaFuncAttributeMaxDynamicSharedMemorySize, 98304);

    k_irfft<<<1, 512>>>(H);
    k_build<<<46, 256>>>(vt, sstd);
    k_conv_mma<<<dim3(4, NB * 6), 256, 98304>>>(noise);
    k_out_mma<<<dim3(CCH / 128, T_OUT / 128, 2), 256, 98304>>>(out);
}

// round 13
// speedup vs baseline: 1.1403x; 1.1403x over previous
#include <cuda_runtime.h>
#include <cuda_fp16.h>
#include <cstdint>
#include <cstring>

// Problem constants
#define T_PADDED 65656
#define T_OUT    65536
#define NROWS    768
#define CCH      384
#define NB       168
#define HOP      392
#define OVL      120
#define NCOLS    (NROWS * NB)   // 129024

#define SWZ(x) ((x) ^ (((x) >> 3) & 0x70))

// ---------------- device globals (allocation-free rule) ----------------
__device__ float  g_h[512];
__device__ uint4  g_Bc[4 * 7 * 1024];              // circulant fp16 tiles [jt][kc], 16KB, SW128
__device__ uint4  g_Bw[3 * 6 * 1024];              // W fp16 tiles [dt][kc]
__device__ __half g_nh[(size_t)NROWS * T_PADDED];  // noise fp16 (rn)
__device__ __half g_C[(size_t)NB * 512 * NROWS];   // fp16 [b][j][r]

// ---------------- helpers ----------------
__device__ __forceinline__ uint32_t smem_u32(const void* p) {
    uint32_t a;
    asm("{ .reg .u64 t; cvta.to.shared.u64 t, %1; cvt.u32.u64 %0, t; }" : "=r"(a) : "l"(p));
    return a;
}
__device__ __forceinline__ void ldm4(uint32_t addr, uint32_t* r) {
    asm volatile("ldmatrix.sync.aligned.m8n8.x4.shared.b16 {%0,%1,%2,%3}, [%4];"
                 : "=r"(r[0]), "=r"(r[1]), "=r"(r[2]), "=r"(r[3]) : "r"(addr));
}
__device__ __forceinline__ void mma16816(float* c, const uint32_t* a, const uint32_t* b) {
    asm volatile("mma.sync.aligned.m16n8k16.row.col.f32.f16.f16.f32 "
                 "{%0,%1,%2,%3},{%4,%5,%6,%7},{%8,%9},{%0,%1,%2,%3};"
                 : "+f"(c[0]), "+f"(c[1]), "+f"(c[2]), "+f"(c[3])
                 : "r"(a[0]), "r"(a[1]), "r"(a[2]), "r"(a[3]), "r"(b[0]), "r"(b[1]));
}
__device__ __forceinline__ unsigned hadd2u(unsigned a, unsigned b) {
    __half2 x, y; memcpy(&x, &a, 4); memcpy(&y, &b, 4);
    __half2 z = __hadd2(x, y);
    unsigned u; memcpy(&u, &z, 4); return u;
}
#define CP16(s, g)     asm volatile("cp.async.cg.shared.global [%0], [%1], 16;" :: "r"(s), "l"(g))
#define CPZ(s, g, sz)  asm volatile("cp.async.cg.shared.global [%0], [%1], 16, %2;" :: "r"(s), "l"(g), "r"(sz))
#define CP_COMMIT()    asm volatile("cp.async.commit_group;" ::: "memory")
#define CP_WAIT1()     asm volatile("cp.async.wait_group 1;" ::: "memory")

// ---------------- kernel 1: h = irfft(H, 512) ----------------
__global__ void k_irfft(const float* __restrict__ H) {
    int j = threadIdx.x;
    float acc = H[0] + ((j & 1) ? -H[256] : H[256]);
    const float w = 6.283185307179586476f / 512.0f;
    for (int m = 1; m < 256; m++) {
        int ph = (m * j) & 511;
        acc += 2.0f * H[m] * cosf(w * (float)ph);
    }
    g_h[j] = acc * (1.0f / 512.0f);
}

// ---------------- kernel 1b: build circulant + W tiles (merged) ----------------
// blocks 0..27: circulant tiles [jt][kc] (jt = blk/7, kc = blk%7)
// blocks 28..45: W tiles [dt][kc]       (dt = w/6,  kc = w%6)
__global__ void k_build(const float* __restrict__ vt, const float* __restrict__ sstd) {
    const int tid = threadIdx.x;
    if (blockIdx.x < 28) {
        __shared__ float sh[512];
        int jt = blockIdx.x / 7, kc = blockIdx.x % 7;
        sh[tid] = g_h[tid]; sh[tid + 256] = g_h[tid + 256];
        __syncthreads();
        char* dst = (char*)g_Bc + (size_t)(jt * 7 + kc) * 16384;
        for (int e = tid; e < 8192; e += 256) {
            int jl = e >> 6, kl = e & 63;
            int k = kc * 64 + kl;
            float v = (k < HOP) ? sh[(jt * 128 + jl - k) & 511] : 0.0f;
            *(__half*)(dst + SWZ(jl * 128 + kl * 2)) = __float2half_rn(v);
        }
    } else {
        int w = blockIdx.x - 28;
        int dt = w / 6, kc = w % 6;
        char* dst = (char*)g_Bw + (size_t)(dt * 6 + kc) * 16384;
        for (int e = tid; e < 8192; e += 256) {
            int kl = e >> 7, dl = e & 127;
            int c = kc * 64 + kl, d = dt * 128 + dl;
            float v = sstd[c] * vt[c * CCH + d];
            *(__half*)(dst + SWZ(dl * 128 + kl * 2)) = __float2half_rn(v);
        }
    }
}

// ---------------- kernel 1d: noise -> fp16 plane ----------------
__global__ void k_trunc_noise(const float* __restrict__ noise) {
    size_t i = ((size_t)blockIdx.x * 256 + threadIdx.x) * 4;
    float4 v = *(const float4*)(noise + i);
    *(__half2*)(g_nh + i)     = __halves2half2(__float2half_rn(v.x), __float2half_rn(v.y));
    *(__half2*)(g_nh + i + 2) = __halves2half2(__float2half_rn(v.z), __float2half_rn(v.w));
}

// ============================================================================
// fp16 warp-MMA engine. Stage s at s*32768: A @+0 (128x128B, SW128), B @+16384.
// 8 warps: wm = wid>>2 (2) x wn = wid&3 (4); warp tile 64m x 32n.
// Both ksteps' B fragments are hoisted ahead of the MMA stream of the half
// (deeper LDSM window for the scheduler). Templated range for interleaving.
// ============================================================================
template <int KS0>
__device__ __forceinline__ void gemm16_pair(uint32_t sb, int s, int wm, int wn,
                                            int lane, float acc[4][4][4]) {
    const uint32_t sx = (lane & 7) << 4;
    const int kA_l = (lane & 16) >> 1;
    const int kB_l = lane & 8;
    const int mrow = lane & 15;
    const int nrow = (lane & 7) + ((lane & 16) >> 1);
    const uint32_t aBase = sb + s * 32768 + (wm * 64 + mrow) * 128;
    const uint32_t bBase = sb + s * 32768 + 16384 + (wn * 32 + nrow) * 128;

    // hoist B fragments for both ksteps of this half
    uint32_t bh[2][4][2];
#pragma unroll
    for (int ks = 0; ks < 2; ks++) {
        const uint32_t kb = ((uint32_t)((KS0 + ks) * 16 + kB_l) * 2) ^ sx;
#pragma unroll
        for (int p = 0; p < 2; p++) {
            uint32_t r[4];
            ldm4(bBase + p * 2048 + kb, r);
            bh[ks][2 * p][0] = r[0]; bh[ks][2 * p][1] = r[1];
            bh[ks][2 * p + 1][0] = r[2]; bh[ks][2 * p + 1][1] = r[3];
        }
    }
#pragma unroll
    for (int ks = 0; ks < 2; ks++) {
        const uint32_t ka = ((uint32_t)((KS0 + ks) * 16 + kA_l) * 2) ^ sx;
#pragma unroll
        for (int mf = 0; mf < 4; mf++) {
            uint32_t ah[4];
            ldm4(aBase + mf * 2048 + ka, ah);
#pragma unroll
            for (int nf = 0; nf < 4; nf++)
                mma16816(acc[mf][nf], ah, bh[ks][nf]);
        }
    }
}

// single-kstep variant (conv tail)
__device__ __forceinline__ void gemm16_one(uint32_t sb, int s, int wm, int wn,
                                           int lane, float acc[4][4][4]) {
    const uint32_t sx = (lane & 7) << 4;
    const int kA_l = (lane & 16) >> 1;
    const int kB_l = lane & 8;
    const int mrow = lane & 15;
    const int nrow = (lane & 7) + ((lane & 16) >> 1);
    const uint32_t aBase = sb + s * 32768 + (wm * 64 + mrow) * 128;
    const uint32_t bBase = sb + s * 32768 + 16384 + (wn * 32 + nrow) * 128;
    const uint32_t ka = ((uint32_t)kA_l * 2) ^ sx;
    const uint32_t kb = ((uint32_t)kB_l * 2) ^ sx;
    uint32_t bh[4][2];
#pragma unroll
    for (int p = 0; p < 2; p++) {
        uint32_t r[4];
        ldm4(bBase + p * 2048 + kb, r);
        bh[2 * p][0] = r[0]; bh[2 * p][1] = r[1];
        bh[2 * p + 1][0] = r[2]; bh[2 * p + 1][1] = r[3];
    }
#pragma unroll
    for (int mf = 0; mf < 4; mf++) {
        uint32_t ah[4];
        ldm4(aBase + mf * 2048 + ka, ah);
#pragma unroll
        for (int nf = 0; nf < 4; nf++)
            mma16816(acc[mf][nf], ah, bh[nf]);
    }
}

// ---------------- kernel 2: conv GEMM ----------------
// D[r][j] for block b: m = r (A = noise fp16 via cp.async), n = j (B = circ tiles).
// Grid (jt, b*6+rt): jt fastest so co-resident CTAs share noise chunks in L2.
// 3-stage pipeline, single sync per chunk, copy-issue interleaved.
// Epilogue transposes through smem -> g_C[b][j][r] (r contiguous).
__global__ __launch_bounds__(256, 2) void k_conv_mma() {
    extern __shared__ char smem[];
    const uint32_t sb = smem_u32(smem);
    const int tid = threadIdx.x, lane = tid & 31, wid = tid >> 5;
    const int wm = wid >> 2, wn = wid & 3;
    const int jt = blockIdx.x;
    const int b  = blockIdx.y / 6;
    const int rt = blockIdx.y % 6;

    const int row = tid >> 1;
    const int seg = (tid & 1) * 64;       // byte offset in row
    const uint32_t rowbase = row * 128;
    const uint32_t rxor = (row & 7) << 4;
    const __half* nrow_ptr = g_nh + (size_t)(rt * 128 + row) * T_PADDED + b * HOP;
    const int krel = T_PADDED - b * HOP;

    float acc[4][4][4];
#pragma unroll
    for (int i = 0; i < 4; i++)
#pragma unroll
        for (int j = 0; j < 4; j++)
#pragma unroll
            for (int q = 0; q < 4; q++) acc[i][j][q] = 0.0f;

#define CONV_ISSUE(cc, s) do { \
    const int kk = (cc) * 64 + seg / 2; \
    _Pragma("unroll") \
    for (int i = 0; i < 4; i++) { \
        unsigned sz = (kk + i * 8 < krel) ? 16u : 0u; \
        CPZ(sb + (s) * 32768 + rowbase + ((seg + i * 16) ^ rxor), nrow_ptr + kk + i * 8, sz); \
    } \
    const char* srcB = (const char*)(g_Bc + (size_t)(jt * 7 + (cc)) * 1024) + tid * 16; \
    uint32_t dB = sb + (s) * 32768 + 16384 + tid * 16; \
    _Pragma("unroll") \
    for (int i = 0; i < 4; i++) CP16(dB + i * 4096, srcB + i * 4096); \
} while (0)

    CONV_ISSUE(0, 0); CP_COMMIT();
    CONV_ISSUE(1, 1); CP_COMMIT();

#pragma unroll 1
    for (int c = 0; c < 6; c++) {
        CP_WAIT1();                        // chunk c landed (this thread)
        __syncthreads();                   // visible to all; stage (c+2)%3 free
        gemm16_pair<0>(sb, c % 3, wm, wn, lane, acc);
        CONV_ISSUE(c + 2, (c + 2) % 3);
        CP_COMMIT();
        gemm16_pair<2>(sb, c % 3, wm, wn, lane, acc);
    }
    // tail chunk c = 6 (1 kstep)
    CP_WAIT1();
    __syncthreads();
    gemm16_one(sb, 0 /* 6%3 */, wm, wn, lane, acc);

    // epilogue: transpose through smem, write g_C[b][j][r] (r contiguous)
    __syncthreads();
    {
        __half* st = (__half*)smem;       // [j][136] halves, 34816 B
#pragma unroll
        for (int mf = 0; mf < 4; mf++) {
            int m = wm * 64 + mf * 16 + (lane >> 2);
#pragma unroll
            for (int nf = 0; nf < 4; nf++) {
                int j = wn * 32 + nf * 8 + (lane & 3) * 2;
                st[j * 136 + m]           = __float2half_rn(acc[mf][nf][0]);
                st[(j + 1) * 136 + m]     = __float2half_rn(acc[mf][nf][1]);
                st[j * 136 + m + 8]       = __float2half_rn(acc[mf][nf][2]);
                st[(j + 1) * 136 + m + 8] = __float2half_rn(acc[mf][nf][3]);
            }
        }
        __syncthreads();
        const int jl = tid >> 1;
        const int sg = (tid & 1) * 64;    // halves
        const uint4* src = (const uint4*)(st + jl * 136 + sg);
        uint4* dst = (uint4*)(g_C + (size_t)(b * 512 + jt * 128 + jl) * 768 + rt * 128 + sg);
#pragma unroll
        for (int i = 0; i < 8; i++) dst[i] = src[i];
    }
#undef CONV_ISSUE
}

// ---------------- kernel 3: fused overlap-add + dewhiten GEMM ----------------
// out[nz][t][d] = sum_c y[t][c] * W[d][c],
//   y[t][c] = C[b2][j2][nz*384+c] (+ C[b2-1][j2+392][nz*384+c] if j2<120)
// m = t (A via LDG + hadd2 + STS), n = d (B = W tiles via cp.async).
// 3-stage, single sync per chunk, copy-issue interleaved between gemm halves.
__global__ __launch_bounds__(256, 2) void k_out_mma(float* __restrict__ out) {
    extern __shared__ char smem[];
    const uint32_t sb = smem_u32(smem);
    const int tid = threadIdx.x, lane = tid & 31, wid = tid >> 5;
    const int wm = wid >> 2, wn = wid & 3;
    const int dt = blockIdx.x;
    const int t0 = blockIdx.y * 128;
    const int nz = blockIdx.z;

    const int row = tid >> 1;
    const int segh = (tid & 1) * 32;      // half offset within chunk
    const int segB = (tid & 1) * 64;      // byte offset
    const uint32_t rowbase = row * 128;
    const uint32_t rxor = (row & 7) << 4;

    const int t = t0 + row;
    const int p = t + OVL;
    const int b2 = p / HOP;
    const int j2 = p - b2 * HOP;
    const __half* ybase = g_C + (size_t)(b2 * 512 + j2) * 768 + nz * CCH;
    const bool ov = (j2 < OVL);

    float acc[4][4][4];
#pragma unroll
    for (int i = 0; i < 4; i++)
#pragma unroll
        for (int j = 0; j < 4; j++)
#pragma unroll
            for (int q = 0; q < 4; q++) acc[i][j][q] = 0.0f;

    uint4 pf[4];

#define OUT_LDG(cc) do { \
    const int kk = (cc) * 64 + segh; \
    _Pragma("unroll") \
    for (int i = 0; i < 4; i++) { \
        uint4 v = *(const uint4*)(ybase + kk + i * 8); \
        if (ov) { \
            uint4 w = *(const uint4*)(ybase + kk + i * 8 - 92160); \
            v.x = hadd2u(v.x, w.x); v.y = hadd2u(v.y, w.y); \
            v.z = hadd2u(v.z, w.z); v.w = hadd2u(v.w, w.w); \
        } \
        pf[i] = v; \
    } \
} while (0)
#define OUT_STS(s) do { \
    _Pragma("unroll") \
    for (int i = 0; i < 4; i++) \
        *(uint4*)(smem + (s) * 32768 + rowbase + ((segB + i * 16) ^ rxor)) = pf[i]; \
} while (0)
#define OUT_CPB(cc, s) do { \
    const char* srcB = (const char*)(g_Bw + (size_t)(dt * 6 + (cc)) * 1024) + tid * 16; \
    uint32_t dB = sb + (s) * 32768 + 16384 + tid * 16; \
    _Pragma("unroll") \
    for (int i = 0; i < 4; i++) CP16(dB + i * 4096, srcB + i * 4096); \
} while (0)

    // prologue: stages 0,1 filled; pf = chunk 2
    OUT_LDG(0); OUT_STS(0);
    OUT_LDG(1); OUT_STS(1);
    OUT_CPB(0, 0); CP_COMMIT();
    OUT_CPB(1, 1); CP_COMMIT();
    OUT_LDG(2);

#pragma unroll 1
    for (int c = 0; c < 6; c++) {
        CP_WAIT1();                        // B(c) landed (this thread)
        __syncthreads();                   // copies + STS(c) visible; stage (c+2)%3 free
        gemm16_pair<0>(sb, c % 3, wm, wn, lane, acc);
        if (c + 2 < 6) {
            OUT_CPB(c + 2, (c + 2) % 3);
            OUT_STS((c + 2) % 3);          // pf holds chunk c+2
        }
        CP_COMMIT();                       // unconditional: 1 group / iteration
        if (c + 3 < 6) OUT_LDG(c + 3);     // refill pf
        gemm16_pair<2>(sb, c % 3, wm, wn, lane, acc);
    }

    // epilogue: out[(nz*T + t)*384 + d]
    const int tb = t0 + wm * 64;
    const int db = dt * 128 + wn * 32;
#pragma unroll
    for (int mf = 0; mf < 4; mf++) {
        int tt = tb + mf * 16 + (lane >> 2);
        float* ob0 = out + ((size_t)nz * T_OUT + tt) * CCH;
        float* ob1 = out + ((size_t)nz * T_OUT + tt + 8) * CCH;
#pragma unroll
        for (int nf = 0; nf < 4; nf++) {
            int d = db + nf * 8 + (lane & 3) * 2;
            *(float2*)(ob0 + d) = make_float2(acc[mf][nf][0], acc[mf][nf][1]);
            *(float2*)(ob1 + d) = make_float2(acc[mf][nf][2], acc[mf][nf][3]);
        }
    }
#undef OUT_LDG
#undef OUT_STS
#undef OUT_CPB
}

// ---------------------------------------------------------------------------
extern "C" void kernel_launch(void* const* d_in, const int* in_sizes, int n_in,
                              void* d_out, int out_size) {
    const float* noise = (const float*)d_in[0];   // [768, 65656]
    const float* sstd  = (const float*)d_in[1];   // [384]
    const float* vt    = (const float*)d_in[2];   // [384, 384]
    const float* H     = (const float*)d_in[3];   // [257]
    float* out = (float*)d_out;                   // [2, 65536, 384]

    cudaFuncSetAttribute(k_conv_mma, cudaFuncAttributeMaxDynamicSharedMemorySize, 98304);
    cudaFuncSetAttribute(k_out_mma,  cudaFuncAttributeMaxDynamicSharedMemorySize, 98304);

    k_irfft<<<1, 512>>>(H);
    k_build<<<46, 256>>>(vt, sstd);
    k_trunc_noise<<<(NROWS * T_PADDED) / 1024, 256>>>(noise);
    k_conv_mma<<<dim3(4, NB * 6), 256, 98304>>>();
    k_out_mma<<<dim3(CCH / 128, T_OUT / 128, 2), 256, 98304>>>(out);
}

// round 14
// speedup vs baseline: 1.1974x; 1.0501x over previous
#include <cuda_runtime.h>
#include <cuda_fp16.h>
#include <cstdint>
#include <cstring>

// Problem constants
#define T_PADDED 65656
#define T_OUT    65536
#define NROWS    768
#define CCH      384
#define NB       168
#define HOP      392
#define OVL      120
#define NCOLS    (NROWS * NB)   // 129024

#define SWZ(x) ((x) ^ (((x) >> 3) & 0x70))

// ---------------- device globals (allocation-free rule) ----------------
__device__ float  g_h[512];
__device__ uint4  g_Bc[4 * 7 * 1024];              // circulant fp16 tiles [jt][kc], 16KB, SW128
__device__ uint4  g_Bw[3 * 6 * 1024];              // W fp16 tiles [dt][kc]
__device__ __half g_nh[(size_t)NROWS * T_PADDED];  // noise fp16 (rn)
__device__ __half g_C[(size_t)NB * 512 * NROWS];   // fp16 [b][j][r]

// ---------------- helpers ----------------
__device__ __forceinline__ uint32_t smem_u32(const void* p) {
    uint32_t a;
    asm("{ .reg .u64 t; cvta.to.shared.u64 t, %1; cvt.u32.u64 %0, t; }" : "=r"(a) : "l"(p));
    return a;
}
__device__ __forceinline__ void ldm4(uint32_t addr, uint32_t* r) {
    asm volatile("ldmatrix.sync.aligned.m8n8.x4.shared.b16 {%0,%1,%2,%3}, [%4];"
                 : "=r"(r[0]), "=r"(r[1]), "=r"(r[2]), "=r"(r[3]) : "r"(addr));
}
__device__ __forceinline__ void mma16816(float* c, const uint32_t* a, const uint32_t* b) {
    asm volatile("mma.sync.aligned.m16n8k16.row.col.f32.f16.f16.f32 "
                 "{%0,%1,%2,%3},{%4,%5,%6,%7},{%8,%9},{%0,%1,%2,%3};"
                 : "+f"(c[0]), "+f"(c[1]), "+f"(c[2]), "+f"(c[3])
                 : "r"(a[0]), "r"(a[1]), "r"(a[2]), "r"(a[3]), "r"(b[0]), "r"(b[1]));
}
__device__ __forceinline__ unsigned hadd2u(unsigned a, unsigned b) {
    __half2 x, y; memcpy(&x, &a, 4); memcpy(&y, &b, 4);
    __half2 z = __hadd2(x, y);
    unsigned u; memcpy(&u, &z, 4); return u;
}
#define CP16(s, g)     asm volatile("cp.async.cg.shared.global [%0], [%1], 16;" :: "r"(s), "l"(g))
#define CPZ(s, g, sz)  asm volatile("cp.async.cg.shared.global [%0], [%1], 16, %2;" :: "r"(s), "l"(g), "r"(sz))
#define CP_COMMIT()    asm volatile("cp.async.commit_group;" ::: "memory")
#define CP_WAIT1()     asm volatile("cp.async.wait_group 1;" ::: "memory")

// ---------------- kernel 1: h = irfft(H, 512) ----------------
__global__ void k_irfft(const float* __restrict__ H) {
    int j = threadIdx.x;
    float acc = H[0] + ((j & 1) ? -H[256] : H[256]);
    const float w = 6.283185307179586476f / 512.0f;
    for (int m = 1; m < 256; m++) {
        int ph = (m * j) & 511;
        acc += 2.0f * H[m] * cosf(w * (float)ph);
    }
    g_h[j] = acc * (1.0f / 512.0f);
}

// ---------------- kernel 1b: build circulant + W tiles (merged) ----------------
__global__ void k_build(const float* __restrict__ vt, const float* __restrict__ sstd) {
    const int tid = threadIdx.x;
    if (blockIdx.x < 28) {
        __shared__ float sh[512];
        int jt = blockIdx.x / 7, kc = blockIdx.x % 7;
        sh[tid] = g_h[tid]; sh[tid + 256] = g_h[tid + 256];
        __syncthreads();
        char* dst = (char*)g_Bc + (size_t)(jt * 7 + kc) * 16384;
        for (int e = tid; e < 8192; e += 256) {
            int jl = e >> 6, kl = e & 63;
            int k = kc * 64 + kl;
            float v = (k < HOP) ? sh[(jt * 128 + jl - k) & 511] : 0.0f;
            *(__half*)(dst + SWZ(jl * 128 + kl * 2)) = __float2half_rn(v);
        }
    } else {
        int w = blockIdx.x - 28;
        int dt = w / 6, kc = w % 6;
        char* dst = (char*)g_Bw + (size_t)(dt * 6 + kc) * 16384;
        for (int e = tid; e < 8192; e += 256) {
            int kl = e >> 7, dl = e & 127;
            int c = kc * 64 + kl, d = dt * 128 + dl;
            float v = sstd[c] * vt[c * CCH + d];
            *(__half*)(dst + SWZ(dl * 128 + kl * 2)) = __float2half_rn(v);
        }
    }
}

// ---------------- kernel 1d: noise -> fp16 plane ----------------
__global__ void k_trunc_noise(const float* __restrict__ noise) {
    size_t i = ((size_t)blockIdx.x * 256 + threadIdx.x) * 4;
    float4 v = *(const float4*)(noise + i);
    *(__half2*)(g_nh + i)     = __halves2half2(__float2half_rn(v.x), __float2half_rn(v.y));
    *(__half2*)(g_nh + i + 2) = __halves2half2(__float2half_rn(v.z), __float2half_rn(v.w));
}

// ============================================================================
// fp16 warp-MMA engine. Stage s at s*32768: A @+0 (128x128B, SW128), B @+16384.
// 8 warps: wm = wid>>2 (2) x wn = wid&3 (4); warp tile 64m x 32n.
// B fragments of both ksteps hoisted ahead of the MMA stream.
// ============================================================================
template <int KS0>
__device__ __forceinline__ void gemm16_pair(uint32_t sb, int s, int wm, int wn,
                                            int lane, float acc[4][4][4]) {
    const uint32_t sx = (lane & 7) << 4;
    const int kA_l = (lane & 16) >> 1;
    const int kB_l = lane & 8;
    const int mrow = lane & 15;
    const int nrow = (lane & 7) + ((lane & 16) >> 1);
    const uint32_t aBase = sb + s * 32768 + (wm * 64 + mrow) * 128;
    const uint32_t bBase = sb + s * 32768 + 16384 + (wn * 32 + nrow) * 128;

    uint32_t bh[2][4][2];
#pragma unroll
    for (int ks = 0; ks < 2; ks++) {
        const uint32_t kb = ((uint32_t)((KS0 + ks) * 16 + kB_l) * 2) ^ sx;
#pragma unroll
        for (int p = 0; p < 2; p++) {
            uint32_t r[4];
            ldm4(bBase + p * 2048 + kb, r);
            bh[ks][2 * p][0] = r[0]; bh[ks][2 * p][1] = r[1];
            bh[ks][2 * p + 1][0] = r[2]; bh[ks][2 * p + 1][1] = r[3];
        }
    }
#pragma unroll
    for (int ks = 0; ks < 2; ks++) {
        const uint32_t ka = ((uint32_t)((KS0 + ks) * 16 + kA_l) * 2) ^ sx;
#pragma unroll
        for (int mf = 0; mf < 4; mf++) {
            uint32_t ah[4];
            ldm4(aBase + mf * 2048 + ka, ah);
#pragma unroll
            for (int nf = 0; nf < 4; nf++)
                mma16816(acc[mf][nf], ah, bh[ks][nf]);
        }
    }
}

// single-kstep variant (conv tail)
__device__ __forceinline__ void gemm16_one(uint32_t sb, int s, int wm, int wn,
                                           int lane, float acc[4][4][4]) {
    const uint32_t sx = (lane & 7) << 4;
    const int kA_l = (lane & 16) >> 1;
    const int kB_l = lane & 8;
    const int mrow = lane & 15;
    const int nrow = (lane & 7) + ((lane & 16) >> 1);
    const uint32_t aBase = sb + s * 32768 + (wm * 64 + mrow) * 128;
    const uint32_t bBase = sb + s * 32768 + 16384 + (wn * 32 + nrow) * 128;
    const uint32_t ka = ((uint32_t)kA_l * 2) ^ sx;
    const uint32_t kb = ((uint32_t)kB_l * 2) ^ sx;
    uint32_t bh[4][2];
#pragma unroll
    for (int p = 0; p < 2; p++) {
        uint32_t r[4];
        ldm4(bBase + p * 2048 + kb, r);
        bh[2 * p][0] = r[0]; bh[2 * p][1] = r[1];
        bh[2 * p + 1][0] = r[2]; bh[2 * p + 1][1] = r[3];
    }
#pragma unroll
    for (int mf = 0; mf < 4; mf++) {
        uint32_t ah[4];
        ldm4(aBase + mf * 2048 + ka, ah);
#pragma unroll
        for (int nf = 0; nf < 4; nf++)
            mma16816(acc[mf][nf], ah, bh[nf]);
    }
}

// ---------------- kernel 2: conv GEMM ----------------
// D[r][j] for block b: m = r (A = noise fp16 via cp.async), n = j (B = circ tiles).
// Grid (jt, b*6+rt): jt fastest so co-resident CTAs share noise chunks in L2.
// 3-stage pipeline, single sync per chunk, copy-issue interleaved.
// Epilogue transposes through smem -> g_C[b][j][r] (r contiguous).
__global__ __launch_bounds__(256, 2) void k_conv_mma() {
    extern __shared__ char smem[];
    const uint32_t sb = smem_u32(smem);
    const int tid = threadIdx.x, lane = tid & 31, wid = tid >> 5;
    const int wm = wid >> 2, wn = wid & 3;
    const int jt = blockIdx.x;
    const int b  = blockIdx.y / 6;
    const int rt = blockIdx.y % 6;

    const int row = tid >> 1;
    const int seg = (tid & 1) * 64;       // byte offset in row
    const uint32_t rowbase = row * 128;
    const uint32_t rxor = (row & 7) << 4;
    const __half* nrow_ptr = g_nh + (size_t)(rt * 128 + row) * T_PADDED + b * HOP;
    const int krel = T_PADDED - b * HOP;

    float acc[4][4][4];
#pragma unroll
    for (int i = 0; i < 4; i++)
#pragma unroll
        for (int j = 0; j < 4; j++)
#pragma unroll
            for (int q = 0; q < 4; q++) acc[i][j][q] = 0.0f;

#define CONV_ISSUE(cc, s) do { \
    const int kk = (cc) * 64 + seg / 2; \
    _Pragma("unroll") \
    for (int i = 0; i < 4; i++) { \
        unsigned sz = (kk + i * 8 < krel) ? 16u : 0u; \
        CPZ(sb + (s) * 32768 + rowbase + ((seg + i * 16) ^ rxor), nrow_ptr + kk + i * 8, sz); \
    } \
    const char* srcB = (const char*)(g_Bc + (size_t)(jt * 7 + (cc)) * 1024) + tid * 16; \
    uint32_t dB = sb + (s) * 32768 + 16384 + tid * 16; \
    _Pragma("unroll") \
    for (int i = 0; i < 4; i++) CP16(dB + i * 4096, srcB + i * 4096); \
} while (0)

    CONV_ISSUE(0, 0); CP_COMMIT();
    CONV_ISSUE(1, 1); CP_COMMIT();

#pragma unroll 1
    for (int c = 0; c < 6; c++) {
        CP_WAIT1();                        // chunk c landed (this thread)
        __syncthreads();                   // visible to all; stage (c+2)%3 free
        gemm16_pair<0>(sb, c % 3, wm, wn, lane, acc);
        CONV_ISSUE(c + 2, (c + 2) % 3);
        CP_COMMIT();
        gemm16_pair<2>(sb, c % 3, wm, wn, lane, acc);
    }
    // tail chunk c = 6 (1 kstep)
    CP_WAIT1();
    __syncthreads();
    gemm16_one(sb, 0 /* 6%3 */, wm, wn, lane, acc);

    // epilogue: transpose through smem, write g_C[b][j][r] (r contiguous)
    __syncthreads();
    {
        __half* st = (__half*)smem;       // [j][136] halves, 34816 B
#pragma unroll
        for (int mf = 0; mf < 4; mf++) {
            int m = wm * 64 + mf * 16 + (lane >> 2);
#pragma unroll
            for (int nf = 0; nf < 4; nf++) {
                int j = wn * 32 + nf * 8 + (lane & 3) * 2;
                st[j * 136 + m]           = __float2half_rn(acc[mf][nf][0]);
                st[(j + 1) * 136 + m]     = __float2half_rn(acc[mf][nf][1]);
                st[j * 136 + m + 8]       = __float2half_rn(acc[mf][nf][2]);
                st[(j + 1) * 136 + m + 8] = __float2half_rn(acc[mf][nf][3]);
            }
        }
        __syncthreads();
        const int jl = tid >> 1;
        const int sg = (tid & 1) * 64;    // halves
        const uint4* src = (const uint4*)(st + jl * 136 + sg);
        uint4* dst = (uint4*)(g_C + (size_t)(b * 512 + jt * 128 + jl) * 768 + rt * 128 + sg);
#pragma unroll
        for (int i = 0; i < 8; i++) dst[i] = src[i];
    }
#undef CONV_ISSUE
}

// ---------------- kernel 2b: overlap pre-add ----------------
// g_C[b][j2][r] += g_C[b-1][j2+392][r] for b in [1,168), j2 in [0,120).
// Read rows (j >= 392) and write rows (j < 120) are disjoint.
__global__ __launch_bounds__(256) void k_oadd() {
    size_t id = (size_t)blockIdx.x * 256 + threadIdx.x;   // < 167*120*96
    int b   = (int)(id / (120 * 96));                     // 0..166 -> block b+1
    int rem = (int)(id % (120 * 96));
    int j2  = rem / 96;
    int rq  = rem % 96;                                   // x8 halves
    __half* dp = g_C + (size_t)((b + 1) * 512 + j2) * 768 + rq * 8;
    const __half* sp = g_C + (size_t)(b * 512 + j2 + HOP) * 768 + rq * 8;
    uint4 d = *(uint4*)dp;
    uint4 s = *(const uint4*)sp;
    d.x = hadd2u(d.x, s.x); d.y = hadd2u(d.y, s.y);
    d.z = hadd2u(d.z, s.z); d.w = hadd2u(d.w, s.w);
    *(uint4*)dp = d;
}

// ---------------- kernel 3: dewhiten GEMM (overlap pre-added) ----------------
// out[nz][t][d] = sum_c y[t][c] * W[d][c],  y[t][c] = g_C[b2][j2][nz*384+c]
// m = t (A = g_C rows via cp.async), n = d (B = W tiles via cp.async).
// Identical pipeline structure to conv: 6 uniform chunks, no tail.
__global__ __launch_bounds__(256, 2) void k_out_mma(float* __restrict__ out) {
    extern __shared__ char smem[];
    const uint32_t sb = smem_u32(smem);
    const int tid = threadIdx.x, lane = tid & 31, wid = tid >> 5;
    const int wm = wid >> 2, wn = wid & 3;
    const int dt = blockIdx.x;
    const int t0 = blockIdx.y * 128;
    const int nz = blockIdx.z;

    const int row = tid >> 1;
    const int seg = (tid & 1) * 64;       // byte offset in row
    const uint32_t rowbase = row * 128;
    const uint32_t rxor = (row & 7) << 4;

    const int t = t0 + row;
    const int p = t + OVL;
    const int b2 = p / HOP;
    const int j2 = p - b2 * HOP;
    const __half* yrow = g_C + (size_t)(b2 * 512 + j2) * 768 + nz * CCH;

    float acc[4][4][4];
#pragma unroll
    for (int i = 0; i < 4; i++)
#pragma unroll
        for (int j = 0; j < 4; j++)
#pragma unroll
            for (int q = 0; q < 4; q++) acc[i][j][q] = 0.0f;

#define OUT_ISSUE(cc, s) do { \
    const int kk = (cc) * 64 + seg / 2; \
    _Pragma("unroll") \
    for (int i = 0; i < 4; i++) \
        CP16(sb + (s) * 32768 + rowbase + ((seg + i * 16) ^ rxor), yrow + kk + i * 8); \
    const char* srcB = (const char*)(g_Bw + (size_t)(dt * 6 + (cc)) * 1024) + tid * 16; \
    uint32_t dB = sb + (s) * 32768 + 16384 + tid * 16; \
    _Pragma("unroll") \
    for (int i = 0; i < 4; i++) CP16(dB + i * 4096, srcB + i * 4096); \
} while (0)

    OUT_ISSUE(0, 0); CP_COMMIT();
    OUT_ISSUE(1, 1); CP_COMMIT();

#pragma unroll 1
    for (int c = 0; c < 6; c++) {
        CP_WAIT1();                        // chunk c landed (this thread)
        __syncthreads();                   // visible to all; stage (c+2)%3 free
        gemm16_pair<0>(sb, c % 3, wm, wn, lane, acc);
        if (c + 2 < 6) OUT_ISSUE(c + 2, (c + 2) % 3);
        CP_COMMIT();                       // unconditional: 1 group / iteration
        gemm16_pair<2>(sb, c % 3, wm, wn, lane, acc);
    }

    // epilogue: out[(nz*T + t)*384 + d]
    const int tb = t0 + wm * 64;
    const int db = dt * 128 + wn * 32;
#pragma unroll
    for (int mf = 0; mf < 4; mf++) {
        int tt = tb + mf * 16 + (lane >> 2);
        float* ob0 = out + ((size_t)nz * T_OUT + tt) * CCH;
        float* ob1 = out + ((size_t)nz * T_OUT + tt + 8) * CCH;
#pragma unroll
        for (int nf = 0; nf < 4; nf++) {
            int d = db + nf * 8 + (lane & 3) * 2;
            *(float2*)(ob0 + d) = make_float2(acc[mf][nf][0], acc[mf][nf][1]);
            *(float2*)(ob1 + d) = make_float2(acc[mf][nf][2], acc[mf][nf][3]);
        }
    }
#undef OUT_ISSUE
}

// ---------------------------------------------------------------------------
extern "C" void kernel_launch(void* const* d_in, const int* in_sizes, int n_in,
                              void* d_out, int out_size) {
    const float* noise = (const float*)d_in[0];   // [768, 65656]
    const float* sstd  = (const float*)d_in[1];   // [384]
    const float* vt    = (const float*)d_in[2];   // [384, 384]
    const float* H     = (const float*)d_in[3];   // [257]
    float* out = (float*)d_out;                   // [2, 65536, 384]

    cudaFuncSetAttribute(k_conv_mma, cudaFuncAttributeMaxDynamicSharedMemorySize, 98304);
    cudaFuncSetAttribute(k_out_mma,  cudaFuncAttributeMaxDynamicSharedMemorySize, 98304);

    k_irfft<<<1, 512>>>(H);
    k_build<<<46, 256>>>(vt, sstd);
    k_trunc_noise<<<(NROWS * T_PADDED) / 1024, 256>>>(noise);
    k_conv_mma<<<dim3(4, NB * 6), 256, 98304>>>();
    k_oadd<<<(167 * 120 * 96) / 256, 256>>>();
    k_out_mma<<<dim3(CCH / 128, T_OUT / 128, 2), 256, 98304>>>(out);
}

// round 15
// speedup vs baseline: 1.3113x; 1.0951x over previous
#include <cuda_runtime.h>
#include <cuda_fp16.h>
#include <cstdint>
#include <cstring>

// Problem constants
#define T_PADDED 65656
#define T_OUT    65536
#define NROWS    768
#define CCH      384
#define NB       168
#define HOP      392
#define OVL      120
#define NCOLS    (NROWS * NB)   // 129024

#define SWZ(x) ((x) ^ (((x) >> 3) & 0x70))

// ---------------- device globals (allocation-free rule) ----------------
__device__ uint4  g_Bc[4 * 7 * 1024];              // circulant fp16 tiles [jt][kc], 16KB, SW128
__device__ uint4  g_Bw[3 * 6 * 1024];              // W fp16 tiles [dt][kc]
__device__ __half g_nh[(size_t)NROWS * T_PADDED];  // noise fp16 (rn)
__device__ __half g_C[(size_t)NB * 512 * NROWS];   // fp16 [b][j][r]

// ---------------- helpers ----------------
__device__ __forceinline__ uint32_t smem_u32(const void* p) {
    uint32_t a;
    asm("{ .reg .u64 t; cvta.to.shared.u64 t, %1; cvt.u32.u64 %0, t; }" : "=r"(a) : "l"(p));
    return a;
}
__device__ __forceinline__ void ldm4(uint32_t addr, uint32_t* r) {
    asm volatile("ldmatrix.sync.aligned.m8n8.x4.shared.b16 {%0,%1,%2,%3}, [%4];"
                 : "=r"(r[0]), "=r"(r[1]), "=r"(r[2]), "=r"(r[3]) : "r"(addr));
}
__device__ __forceinline__ void mma16816(float* c, const uint32_t* a, const uint32_t* b) {
    asm volatile("mma.sync.aligned.m16n8k16.row.col.f32.f16.f16.f32 "
                 "{%0,%1,%2,%3},{%4,%5,%6,%7},{%8,%9},{%0,%1,%2,%3};"
                 : "+f"(c[0]), "+f"(c[1]), "+f"(c[2]), "+f"(c[3])
                 : "r"(a[0]), "r"(a[1]), "r"(a[2]), "r"(a[3]), "r"(b[0]), "r"(b[1]));
}
__device__ __forceinline__ unsigned hadd2u(unsigned a, unsigned b) {
    __half2 x, y; memcpy(&x, &a, 4); memcpy(&y, &b, 4);
    __half2 z = __hadd2(x, y);
    unsigned u; memcpy(&u, &z, 4); return u;
}
__device__ __forceinline__ unsigned f22u(float a, float b) {
    __half2 h = __floats2half2_rn(a, b);
    unsigned u; memcpy(&u, &h, 4); return u;
}
#define CP16(s, g)     asm volatile("cp.async.cg.shared.global [%0], [%1], 16;" :: "r"(s), "l"(g))
#define CPZ(s, g, sz)  asm volatile("cp.async.cg.shared.global [%0], [%1], 16, %2;" :: "r"(s), "l"(g), "r"(sz))
#define CP_COMMIT()    asm volatile("cp.async.commit_group;" ::: "memory")
#define CP_WAIT1()     asm volatile("cp.async.wait_group 1;" ::: "memory")
#define CP_WAIT0()     asm volatile("cp.async.wait_group 0;" ::: "memory")

// ---------------- kernel 1: merged prep ----------------
// blocks 0..27:   circulant tiles [jt][kc] (h recomputed locally, identical math)
// blocks 28..45:  W tiles [dt][kc]
// blocks 46.. :   noise -> fp16 plane (8 floats/thread, uint4 store)
#define PREP_TRUNC_BLOCKS ((NROWS * T_PADDED) / (256 * 8))   // 24621
__global__ void k_prep(const float* __restrict__ noise,
                       const float* __restrict__ vt,
                       const float* __restrict__ sstd,
                       const float* __restrict__ H) {
    const int tid = threadIdx.x;
    if (blockIdx.x < 28) {
        __shared__ float sh[512];
        // inline irfft: each thread computes h[tid], h[tid+256] (identical math to before)
        for (int jj = 0; jj < 2; jj++) {
            int j = tid + jj * 256;
            float acc = H[0] + ((j & 1) ? -H[256] : H[256]);
            const float w = 6.283185307179586476f / 512.0f;
            for (int m = 1; m < 256; m++) {
                int ph = (m * j) & 511;
                acc += 2.0f * H[m] * cosf(w * (float)ph);
            }
            sh[j] = acc * (1.0f / 512.0f);
        }
        __syncthreads();
        int jt = blockIdx.x / 7, kc = blockIdx.x % 7;
        char* dst = (char*)g_Bc + (size_t)(jt * 7 + kc) * 16384;
        for (int e = tid; e < 8192; e += 256) {
            int jl = e >> 6, kl = e & 63;
            int k = kc * 64 + kl;
            float v = (k < HOP) ? sh[(jt * 128 + jl - k) & 511] : 0.0f;
            *(__half*)(dst + SWZ(jl * 128 + kl * 2)) = __float2half_rn(v);
        }
    } else if (blockIdx.x < 46) {
        int w = blockIdx.x - 28;
        int dt = w / 6, kc = w % 6;
        char* dst = (char*)g_Bw + (size_t)(dt * 6 + kc) * 16384;
        for (int e = tid; e < 8192; e += 256) {
            int kl = e >> 7, dl = e & 127;
            int c = kc * 64 + kl, d = dt * 128 + dl;
            float v = sstd[c] * vt[c * CCH + d];
            *(__half*)(dst + SWZ(dl * 128 + kl * 2)) = __float2half_rn(v);
        }
    } else {
        size_t i = ((size_t)(blockIdx.x - 46) * 256 + tid) * 8;
        float4 a = *(const float4*)(noise + i);
        float4 b = *(const float4*)(noise + i + 4);
        uint4 o;
        o.x = f22u(a.x, a.y); o.y = f22u(a.z, a.w);
        o.z = f22u(b.x, b.y); o.w = f22u(b.z, b.w);
        *(uint4*)(g_nh + i) = o;
    }
}

// ============================================================================
// fp16 warp-MMA engine. Stage s at s*32768: A @+0 (128x128B, SW128), B @+16384.
// 8 warps: wm = wid>>2 (2) x wn = wid&3 (4); warp tile 64m x 32n.
// B fragments of both ksteps hoisted ahead of the MMA stream.
// ============================================================================
template <int KS0>
__device__ __forceinline__ void gemm16_pair(uint32_t sb, int s, int wm, int wn,
                                            int lane, float acc[4][4][4]) {
    const uint32_t sx = (lane & 7) << 4;
    const int kA_l = (lane & 16) >> 1;
    const int kB_l = lane & 8;
    const int mrow = lane & 15;
    const int nrow = (lane & 7) + ((lane & 16) >> 1);
    const uint32_t aBase = sb + s * 32768 + (wm * 64 + mrow) * 128;
    const uint32_t bBase = sb + s * 32768 + 16384 + (wn * 32 + nrow) * 128;

    uint32_t bh[2][4][2];
#pragma unroll
    for (int ks = 0; ks < 2; ks++) {
        const uint32_t kb = ((uint32_t)((KS0 + ks) * 16 + kB_l) * 2) ^ sx;
#pragma unroll
        for (int p = 0; p < 2; p++) {
            uint32_t r[4];
            ldm4(bBase + p * 2048 + kb, r);
            bh[ks][2 * p][0] = r[0]; bh[ks][2 * p][1] = r[1];
            bh[ks][2 * p + 1][0] = r[2]; bh[ks][2 * p + 1][1] = r[3];
        }
    }
#pragma unroll
    for (int ks = 0; ks < 2; ks++) {
        const uint32_t ka = ((uint32_t)((KS0 + ks) * 16 + kA_l) * 2) ^ sx;
#pragma unroll
        for (int mf = 0; mf < 4; mf++) {
            uint32_t ah[4];
            ldm4(aBase + mf * 2048 + ka, ah);
#pragma unroll
            for (int nf = 0; nf < 4; nf++)
                mma16816(acc[mf][nf], ah, bh[ks][nf]);
        }
    }
}

// single-kstep variant (conv tail)
__device__ __forceinline__ void gemm16_one(uint32_t sb, int s, int wm, int wn,
                                           int lane, float acc[4][4][4]) {
    const uint32_t sx = (lane & 7) << 4;
    const int kA_l = (lane & 16) >> 1;
    const int kB_l = lane & 8;
    const int mrow = lane & 15;
    const int nrow = (lane & 7) + ((lane & 16) >> 1);
    const uint32_t aBase = sb + s * 32768 + (wm * 64 + mrow) * 128;
    const uint32_t bBase = sb + s * 32768 + 16384 + (wn * 32 + nrow) * 128;
    const uint32_t ka = ((uint32_t)kA_l * 2) ^ sx;
    const uint32_t kb = ((uint32_t)kB_l * 2) ^ sx;
    uint32_t bh[4][2];
#pragma unroll
    for (int p = 0; p < 2; p++) {
        uint32_t r[4];
        ldm4(bBase + p * 2048 + kb, r);
        bh[2 * p][0] = r[0]; bh[2 * p][1] = r[1];
        bh[2 * p + 1][0] = r[2]; bh[2 * p + 1][1] = r[3];
    }
#pragma unroll
    for (int mf = 0; mf < 4; mf++) {
        uint32_t ah[4];
        ldm4(aBase + mf * 2048 + ka, ah);
#pragma unroll
        for (int nf = 0; nf < 4; nf++)
            mma16816(acc[mf][nf], ah, bh[nf]);
    }
}

// ---------------- kernel 2: conv GEMM ----------------
// D[r][j] for block b: m = r (A = noise fp16 via cp.async), n = j (B = circ tiles).
// Grid (jt, b*6+rt): jt fastest so co-resident CTAs share noise chunks in L2.
// 3-stage pipeline, single sync per chunk; tail chunk folded into final drain.
// Epilogue transposes through smem -> g_C[b][j][r] (r contiguous).
__global__ __launch_bounds__(256, 2) void k_conv_mma() {
    extern __shared__ char smem[];
    const uint32_t sb = smem_u32(smem);
    const int tid = threadIdx.x, lane = tid & 31, wid = tid >> 5;
    const int wm = wid >> 2, wn = wid & 3;
    const int jt = blockIdx.x;
    const int b  = blockIdx.y / 6;
    const int rt = blockIdx.y % 6;

    const int row = tid >> 1;
    const int seg = (tid & 1) * 64;       // byte offset in row
    const uint32_t rowbase = row * 128;
    const uint32_t rxor = (row & 7) << 4;
    const __half* nrow_ptr = g_nh + (size_t)(rt * 128 + row) * T_PADDED + b * HOP;
    const int krel = T_PADDED - b * HOP;

    float acc[4][4][4];
#pragma unroll
    for (int i = 0; i < 4; i++)
#pragma unroll
        for (int j = 0; j < 4; j++)
#pragma unroll
            for (int q = 0; q < 4; q++) acc[i][j][q] = 0.0f;

#define CONV_ISSUE(cc, s) do { \
    const int kk = (cc) * 64 + seg / 2; \
    _Pragma("unroll") \
    for (int i = 0; i < 4; i++) { \
        unsigned sz = (kk + i * 8 < krel) ? 16u : 0u; \
        CPZ(sb + (s) * 32768 + rowbase + ((seg + i * 16) ^ rxor), nrow_ptr + kk + i * 8, sz); \
    } \
    const char* srcB = (const char*)(g_Bc + (size_t)(jt * 7 + (cc)) * 1024) + tid * 16; \
    uint32_t dB = sb + (s) * 32768 + 16384 + tid * 16; \
    _Pragma("unroll") \
    for (int i = 0; i < 4; i++) CP16(dB + i * 4096, srcB + i * 4096); \
} while (0)

    CONV_ISSUE(0, 0); CP_COMMIT();
    CONV_ISSUE(1, 1); CP_COMMIT();

#pragma unroll 1
    for (int c = 0; c < 5; c++) {
        CP_WAIT1();                        // chunk c landed (this thread)
        __syncthreads();                   // visible to all; stage (c+2)%3 free
        gemm16_pair<0>(sb, c % 3, wm, wn, lane, acc);
        CONV_ISSUE(c + 2, (c + 2) % 3);
        CP_COMMIT();
        gemm16_pair<2>(sb, c % 3, wm, wn, lane, acc);
    }
    // final drain: chunks 5 (stage 2) and 6 (stage 0) both in flight
    CP_WAIT0();
    __syncthreads();
    gemm16_pair<0>(sb, 2, wm, wn, lane, acc);
    gemm16_pair<2>(sb, 2, wm, wn, lane, acc);
    gemm16_one(sb, 0, wm, wn, lane, acc);   // chunk 6: 1 kstep

    // epilogue: transpose through smem, write g_C[b][j][r] (r contiguous)
    __syncthreads();
    {
        __half* st = (__half*)smem;       // [j][136] halves, 34816 B
#pragma unroll
        for (int mf = 0; mf < 4; mf++) {
            int m = wm * 64 + mf * 16 + (lane >> 2);
#pragma unroll
            for (int nf = 0; nf < 4; nf++) {
                int j = wn * 32 + nf * 8 + (lane & 3) * 2;
                st[j * 136 + m]           = __float2half_rn(acc[mf][nf][0]);
                st[(j + 1) * 136 + m]     = __float2half_rn(acc[mf][nf][1]);
                st[j * 136 + m + 8]       = __float2half_rn(acc[mf][nf][2]);
                st[(j + 1) * 136 + m + 8] = __float2half_rn(acc[mf][nf][3]);
            }
        }
        __syncthreads();
        const int jl = tid >> 1;
        const int sg = (tid & 1) * 64;    // halves
        const uint4* src = (const uint4*)(st + jl * 136 + sg);
        uint4* dst = (uint4*)(g_C + (size_t)(b * 512 + jt * 128 + jl) * 768 + rt * 128 + sg);
#pragma unroll
        for (int i = 0; i < 8; i++) dst[i] = src[i];
    }
#undef CONV_ISSUE
}

// ---------------- kernel 2b: overlap pre-add ----------------
// g_C[b][j2][r] += g_C[b-1][j2+392][r] for b in [1,168), j2 in [0,120).
__global__ __launch_bounds__(256) void k_oadd() {
    size_t id = (size_t)blockIdx.x * 256 + threadIdx.x;   // < 167*120*96
    int b   = (int)(id / (120 * 96));
    int rem = (int)(id % (120 * 96));
    int j2  = rem / 96;
    int rq  = rem % 96;                                   // x8 halves
    __half* dp = g_C + (size_t)((b + 1) * 512 + j2) * 768 + rq * 8;
    const __half* sp = g_C + (size_t)(b * 512 + j2 + HOP) * 768 + rq * 8;
    uint4 d = *(uint4*)dp;
    uint4 s = *(const uint4*)sp;
    d.x = hadd2u(d.x, s.x); d.y = hadd2u(d.y, s.y);
    d.z = hadd2u(d.z, s.z); d.w = hadd2u(d.w, s.w);
    *(uint4*)dp = d;
}

// ---------------- kernel 3: dewhiten GEMM (overlap pre-added) ----------------
// out[nz][t][d] = sum_c y[t][c] * W[d][c],  y[t][c] = g_C[b2][j2][nz*384+c]
// m = t (A = g_C rows via cp.async), n = d (B = W tiles via cp.async).
__global__ __launch_bounds__(256, 2) void k_out_mma(float* __restrict__ out) {
    extern __shared__ char smem[];
    const uint32_t sb = smem_u32(smem);
    const int tid = threadIdx.x, lane = tid & 31, wid = tid >> 5;
    const int wm = wid >> 2, wn = wid & 3;
    const int dt = blockIdx.x;
    const int t0 = blockIdx.y * 128;
    const int nz = blockIdx.z;

    const int row = tid >> 1;
    const int seg = (tid & 1) * 64;       // byte offset in row
    const uint32_t rowbase = row * 128;
    const uint32_t rxor = (row & 7) << 4;

    const int t = t0 + row;
    const int p = t + OVL;
    const int b2 = p / HOP;
    const int j2 = p - b2 * HOP;
    const __half* yrow = g_C + (size_t)(b2 * 512 + j2) * 768 + nz * CCH;

    float acc[4][4][4];
#pragma unroll
    for (int i = 0; i < 4; i++)
#pragma unroll
        for (int j = 0; j < 4; j++)
#pragma unroll
            for (int q = 0; q < 4; q++) acc[i][j][q] = 0.0f;

#define OUT_ISSUE(cc, s) do { \
    const int kk = (cc) * 64 + seg / 2; \
    _Pragma("unroll") \
    for (int i = 0; i < 4; i++) \
        CP16(sb + (s) * 32768 + rowbase + ((seg + i * 16) ^ rxor), yrow + kk + i * 8); \
    const char* srcB = (const char*)(g_Bw + (size_t)(dt * 6 + (cc)) * 1024) + tid * 16; \
    uint32_t dB = sb + (s) * 32768 + 16384 + tid * 16; \
    _Pragma("unroll") \
    for (int i = 0; i < 4; i++) CP16(dB + i * 4096, srcB + i * 4096); \
} while (0)

    OUT_ISSUE(0, 0); CP_COMMIT();
    OUT_ISSUE(1, 1); CP_COMMIT();

#pragma unroll 1
    for (int c = 0; c < 6; c++) {
        CP_WAIT1();                        // chunk c landed (this thread)
        __syncthreads();                   // visible to all; stage (c+2)%3 free
        gemm16_pair<0>(sb, c % 3, wm, wn, lane, acc);
        if (c + 2 < 6) OUT_ISSUE(c + 2, (c + 2) % 3);
        CP_COMMIT();                       // unconditional: 1 group / iteration
        gemm16_pair<2>(sb, c % 3, wm, wn, lane, acc);
    }

    // epilogue: out[(nz*T + t)*384 + d]
    const int tb = t0 + wm * 64;
    const int db = dt * 128 + wn * 32;
#pragma unroll
    for (int mf = 0; mf < 4; mf++) {
        int tt = tb + mf * 16 + (lane >> 2);
        float* ob0 = out + ((size_t)nz * T_OUT + tt) * CCH;
        float* ob1 = out + ((size_t)nz * T_OUT + tt + 8) * CCH;
#pragma unroll
        for (int nf = 0; nf < 4; nf++) {
            int d = db + nf * 8 + (lane & 3) * 2;
            *(float2*)(ob0 + d) = make_float2(acc[mf][nf][0], acc[mf][nf][1]);
            *(float2*)(ob1 + d) = make_float2(acc[mf][nf][2], acc[mf][nf][3]);
        }
    }
#undef OUT_ISSUE
}

// ---------------------------------------------------------------------------
extern "C" void kernel_launch(void* const* d_in, const int* in_sizes, int n_in,
                              void* d_out, int out_size) {
    const float* noise = (const float*)d_in[0];   // [768, 65656]
    const float* sstd  = (const float*)d_in[1];   // [384]
    const float* vt    = (const float*)d_in[2];   // [384, 384]
    const float* H     = (const float*)d_in[3];   // [257]
    float* out = (float*)d_out;                   // [2, 65536, 384]

    cudaFuncSetAttribute(k_conv_mma, cudaFuncAttributeMaxDynamicSharedMemorySize, 98304);
    cudaFuncSetAttribute(k_out_mma,  cudaFuncAttributeMaxDynamicSharedMemorySize, 98304);

    k_prep<<<46 + PREP_TRUNC_BLOCKS, 256>>>(noise, vt, sstd, H);
    k_conv_mma<<<dim3(4, NB * 6), 256, 98304>>>();
    k_oadd<<<(167 * 120 * 96) / 256, 256>>>();
    k_out_mma<<<dim3(CCH / 128, T_OUT / 128, 2), 256, 98304>>>(out);
}